// round 2
// baseline (speedup 1.0000x reference)
#include <cuda_runtime.h>
#include <math.h>

#define Bc 16
#define Nc 16384
#define Kc 8
#define DIMc 256
#define Hc 4
#define DHc 64
#define EPSc 1e-8f
#define SCALEc 0.125f

// ---------------- scratch (static device globals; no allocation) ----------------
__device__ float g_k[(size_t)Bc * Nc * DIMc];      // 256 MB
__device__ float g_v[(size_t)Bc * Nc * DIMc];      // 256 MB
__device__ float g_attn[(size_t)Bc * Nc * 32];     // 32 MB  [b][n][i*4+h]
__device__ float g_mu[Bc * Nc];
__device__ float g_rstd[Bc * Nc];
__device__ float g_Wg[512 * 256];                  // folded [k;v] weights * ln_in_g
__device__ float g_s1[512];
__device__ float g_s2[512];
__device__ float g_q[128 * 256];                   // [b*8+i][h*64+d]
__device__ float g_S[16 * 32];                     // attn row sums [b][i*4+h]
__device__ float g_upd[128 * 256];
__device__ float g_slots[128 * 256];
__device__ float g_ff[128 * 1024];

__device__ __forceinline__ float sigmoidf_(float x) { return 1.0f / (1.0f + expf(-x)); }

// ---------------- prep: fold ln_in gamma/beta into K/V weights ----------------
__global__ void prep_fold(const float* __restrict__ wk, const float* __restrict__ wv,
                          const float* __restrict__ g, const float* __restrict__ b) {
    int j = blockIdx.x;           // 0..511
    int c = threadIdx.x;          // 0..255
    const float* W = (j < 256) ? (wk + (size_t)j * 256) : (wv + (size_t)(j - 256) * 256);
    float w = W[c];
    float wg = w * g[c];
    float wb = w * b[c];
    g_Wg[j * 256 + c] = wg;
    __shared__ float r1[8], r2[8];
    float a = wg, bb = wb;
#pragma unroll
    for (int o = 16; o; o >>= 1) {
        a += __shfl_xor_sync(0xffffffffu, a, o);
        bb += __shfl_xor_sync(0xffffffffu, bb, o);
    }
    if ((c & 31) == 0) { r1[c >> 5] = a; r2[c >> 5] = bb; }
    __syncthreads();
    if (c == 0) {
        float s1 = 0.f, s2 = 0.f;
#pragma unroll
        for (int u = 0; u < 8; u++) { s1 += r1[u]; s2 += r2[u]; }
        g_s1[j] = s1; g_s2[j] = s2;
    }
}

// ---------------- row stats of inputs (mean / rstd) ----------------
__global__ void rowstats(const float* __restrict__ x) {
    int row = blockIdx.x * 8 + (threadIdx.x >> 5);
    int lane = threadIdx.x & 31;
    const float* xr = x + (size_t)row * 256;
    float s = 0.f, s2 = 0.f;
#pragma unroll
    for (int u = 0; u < 8; u++) {
        float v = xr[lane + u * 32];
        s += v; s2 += v * v;
    }
#pragma unroll
    for (int o = 16; o; o >>= 1) {
        s += __shfl_xor_sync(0xffffffffu, s, o);
        s2 += __shfl_xor_sync(0xffffffffu, s2, o);
    }
    if (lane == 0) {
        float m = s * (1.0f / 256.0f);
        float var = s2 * (1.0f / 256.0f) - m * m;
        g_mu[row] = m;
        g_rstd[row] = rsqrtf(var + 1e-5f);
    }
}

// ---------------- big GEMM: C[M,512] = x[M,256] @ Wg^T, with LN epilogue ----------------
// BM=128 BN=128 BK=16, 256 threads, 8x8 per thread
__global__ void kv_gemm(const float* __restrict__ x) {
    __shared__ float As[16][128];
    __shared__ float Bs[16][132];
    int bm = blockIdx.y * 128;
    int bn = blockIdx.x * 128;
    int tid = threadIdx.x;
    int tx = tid & 15, ty = tid >> 4;
    float acc[8][8];
#pragma unroll
    for (int i = 0; i < 8; i++)
#pragma unroll
        for (int j = 0; j < 8; j++) acc[i][j] = 0.f;

    int aRow = tid >> 1;
    int aCol = (tid & 1) * 8;

    for (int k0 = 0; k0 < 256; k0 += 16) {
        float4 a0 = *(const float4*)&x[(size_t)(bm + aRow) * 256 + k0 + aCol];
        float4 a1 = *(const float4*)&x[(size_t)(bm + aRow) * 256 + k0 + aCol + 4];
        float4 b0 = *(const float4*)&g_Wg[(size_t)(bn + aRow) * 256 + k0 + aCol];
        float4 b1 = *(const float4*)&g_Wg[(size_t)(bn + aRow) * 256 + k0 + aCol + 4];
        As[aCol + 0][aRow] = a0.x; As[aCol + 1][aRow] = a0.y;
        As[aCol + 2][aRow] = a0.z; As[aCol + 3][aRow] = a0.w;
        As[aCol + 4][aRow] = a1.x; As[aCol + 5][aRow] = a1.y;
        As[aCol + 6][aRow] = a1.z; As[aCol + 7][aRow] = a1.w;
        Bs[aCol + 0][aRow] = b0.x; Bs[aCol + 1][aRow] = b0.y;
        Bs[aCol + 2][aRow] = b0.z; Bs[aCol + 3][aRow] = b0.w;
        Bs[aCol + 4][aRow] = b1.x; Bs[aCol + 5][aRow] = b1.y;
        Bs[aCol + 6][aRow] = b1.z; Bs[aCol + 7][aRow] = b1.w;
        __syncthreads();
#pragma unroll
        for (int kk = 0; kk < 16; kk++) {
            float4 av0 = *(float4*)&As[kk][ty * 8];
            float4 av1 = *(float4*)&As[kk][ty * 8 + 4];
            float4 bv0 = *(float4*)&Bs[kk][tx * 8];
            float4 bv1 = *(float4*)&Bs[kk][tx * 8 + 4];
            float a[8] = {av0.x, av0.y, av0.z, av0.w, av1.x, av1.y, av1.z, av1.w};
            float b[8] = {bv0.x, bv0.y, bv0.z, bv0.w, bv1.x, bv1.y, bv1.z, bv1.w};
#pragma unroll
            for (int i = 0; i < 8; i++)
#pragma unroll
                for (int j = 0; j < 8; j++) acc[i][j] += a[i] * b[j];
        }
        __syncthreads();
    }

    bool isk = (bn < 256);
    float* dst = isk ? g_k : g_v;
    int cb = isk ? bn : (bn - 256);
    float s1l[8], s2l[8];
#pragma unroll
    for (int j = 0; j < 8; j++) {
        int col = bn + tx * 8 + j;
        s1l[j] = g_s1[col]; s2l[j] = g_s2[col];
    }
#pragma unroll
    for (int i = 0; i < 8; i++) {
        int row = bm + ty * 8 + i;
        float m = g_mu[row], rs = g_rstd[row];
        float o[8];
#pragma unroll
        for (int j = 0; j < 8; j++) o[j] = rs * (acc[i][j] - m * s1l[j]) + s2l[j];
        float4* p = (float4*)&dst[(size_t)row * 256 + cb + tx * 8];
        p[0] = make_float4(o[0], o[1], o[2], o[3]);
        p[1] = make_float4(o[4], o[5], o[6], o[7]);
    }
}

// ---------------- q projection: q = LN(slots; ln_s) @ w_q^T ----------------
__global__ void qproj(const float* __restrict__ wq, const float* __restrict__ lng,
                      const float* __restrict__ lnb) {
    __shared__ float xs[8][256];
    __shared__ float mu8[8], rs8[8];
    int rb = blockIdx.x * 8;
    int t = threadIdx.x, w = t >> 5, lane = t & 31;
    {
        const float* sr = &g_slots[(rb + w) * 256];
        float s = 0.f, s2 = 0.f;
#pragma unroll
        for (int u = 0; u < 8; u++) { float v = sr[lane + u * 32]; s += v; s2 += v * v; }
#pragma unroll
        for (int o = 16; o; o >>= 1) {
            s += __shfl_xor_sync(0xffffffffu, s, o);
            s2 += __shfl_xor_sync(0xffffffffu, s2, o);
        }
        if (lane == 0) {
            float m = s * (1.0f / 256.0f);
            float var = s2 * (1.0f / 256.0f) - m * m;
            mu8[w] = m; rs8[w] = rsqrtf(var + 1e-5f);
        }
    }
    __syncthreads();
    float gg = lng[t], bb = lnb[t];
#pragma unroll
    for (int r = 0; r < 8; r++)
        xs[r][t] = (g_slots[(rb + r) * 256 + t] - mu8[r]) * rs8[r] * gg + bb;
    __syncthreads();
    float acc[8] = {0, 0, 0, 0, 0, 0, 0, 0};
    const float* wr = &wq[(size_t)t * 256];
    for (int cc = 0; cc < 256; cc++) {
        float wv = wr[cc];
#pragma unroll
        for (int r = 0; r < 8; r++) acc[r] += xs[r][cc] * wv;
    }
#pragma unroll
    for (int r = 0; r < 8; r++) g_q[(rb + r) * 256 + t] = acc[r];
}

// ---------------- dots + inverted softmax + attn_out + row sums ----------------
__global__ void dots_kernel(float* __restrict__ ao) {
    __shared__ float ks[32][260];
    __shared__ float qs[8][260];
    __shared__ float sred[32][33];
    int b = blockIdx.y;
    int n0 = blockIdx.x * 512;
    int t = threadIdx.x;
#pragma unroll
    for (int u = 0; u < 2; u++) {
        int l = u * 256 + t;
        int i = l >> 6, c4 = l & 63;
        *(float4*)&qs[i][c4 * 4] = *(const float4*)&g_q[(b * 8 + i) * 256 + c4 * 4];
    }
    int n_l = t >> 3, i = t & 7;
    float sacc[4] = {0, 0, 0, 0};
    for (int tile = 0; tile < 16; tile++) {
        int nt = n0 + tile * 32;
        __syncthreads();
#pragma unroll
        for (int u = 0; u < 8; u++) {
            int l = u * 256 + t;
            int r = l >> 6, c4 = l & 63;
            *(float4*)&ks[r][c4 * 4] =
                *(const float4*)&g_k[((size_t)b * Nc + nt + r) * 256 + c4 * 4];
        }
        __syncthreads();
        float dot[4] = {0, 0, 0, 0};
#pragma unroll
        for (int d4 = 0; d4 < 64; d4++) {
            float4 kk = *(float4*)&ks[n_l][d4 * 4];
            float4 qq = *(float4*)&qs[i][d4 * 4];
            int h = d4 >> 4;
            dot[h] += kk.x * qq.x + kk.y * qq.y + kk.z * qq.z + kk.w * qq.w;
        }
#pragma unroll
        for (int h = 0; h < 4; h++) dot[h] *= SCALEc;
        float m = fmaxf(fmaxf(dot[0], dot[1]), fmaxf(dot[2], dot[3]));
#pragma unroll
        for (int o = 1; o < 8; o <<= 1) m = fmaxf(m, __shfl_xor_sync(0xffffffffu, m, o));
        float e0 = __expf(dot[0] - m), e1 = __expf(dot[1] - m);
        float e2 = __expf(dot[2] - m), e3 = __expf(dot[3] - m);
        float s = e0 + e1 + e2 + e3;
#pragma unroll
        for (int o = 1; o < 8; o <<= 1) s += __shfl_xor_sync(0xffffffffu, s, o);
        float inv = 1.0f / s;
        float4 av = make_float4(e0 * inv, e1 * inv, e2 * inv, e3 * inv);
        int n = nt + n_l;
        *(float4*)&g_attn[((size_t)b * Nc + n) * 32 + i * 4] = av;
        sacc[0] += av.x; sacc[1] += av.y; sacc[2] += av.z; sacc[3] += av.w;
        if (ao) ao[(size_t)(b * 8 + i) * Nc + n] = (av.x + av.y + av.z + av.w) * 0.25f;
    }
    sred[n_l][i * 4 + 0] = sacc[0];
    sred[n_l][i * 4 + 1] = sacc[1];
    sred[n_l][i * 4 + 2] = sacc[2];
    sred[n_l][i * 4 + 3] = sacc[3];
    __syncthreads();
    if (t < 32) {
        float s = 0.f;
#pragma unroll
        for (int nl = 0; nl < 32; nl++) s += sred[nl][t];
        atomicAdd(&g_S[b * 32 + t], s);
    }
}

// ---------------- updates: upd[b,i,h,d] = sum_n attnN * v ----------------
__global__ void upd_kernel() {
    __shared__ float vt[64][68];
    __shared__ float at[64][8];
    __shared__ float ivs[8];
    int b = blockIdx.z, h = blockIdx.y, ch = blockIdx.x;
    int t = threadIdx.x;
    int d = t & 63, sub = t >> 6;
    if (t < 8) ivs[t] = 1.0f / (g_S[b * 32 + t * 4 + h] + EPSc);
    __syncthreads();
    float acc[8] = {0, 0, 0, 0, 0, 0, 0, 0};
    for (int tile = 0; tile < 64; tile++) {
        int nt = ch * 4096 + tile * 64;
        __syncthreads();
#pragma unroll
        for (int u = 0; u < 4; u++) {
            int l = u * 256 + t;
            int r = l >> 4, c4 = l & 15;
            *(float4*)&vt[r][c4 * 4] =
                *(const float4*)&g_v[((size_t)b * Nc + nt + r) * 256 + h * 64 + c4 * 4];
        }
#pragma unroll
        for (int u = 0; u < 2; u++) {
            int l = u * 256 + t;
            int r = l >> 3, ii = l & 7;
            float raw = g_attn[((size_t)b * Nc + nt + r) * 32 + ii * 4 + h];
            at[r][ii] = (raw + EPSc) * ivs[ii];
        }
        __syncthreads();
#pragma unroll
        for (int nn = 0; nn < 16; nn++) {
            int nl = nn * 4 + sub;
            float vv = vt[nl][d];
            float4 a0 = *(float4*)&at[nl][0];
            float4 a1 = *(float4*)&at[nl][4];
            acc[0] += a0.x * vv; acc[1] += a0.y * vv;
            acc[2] += a0.z * vv; acc[3] += a0.w * vv;
            acc[4] += a1.x * vv; acc[5] += a1.y * vv;
            acc[6] += a1.z * vv; acc[7] += a1.w * vv;
        }
    }
    __syncthreads();
    float* red = &vt[0][0];
#pragma unroll
    for (int i = 0; i < 8; i++) red[(sub * 64 + d) * 8 + i] = acc[i];
    __syncthreads();
    if (sub == 0) {
#pragma unroll
        for (int i = 0; i < 8; i++) {
            float s = red[(0 * 64 + d) * 8 + i] + red[(1 * 64 + d) * 8 + i] +
                      red[(2 * 64 + d) * 8 + i] + red[(3 * 64 + d) * 8 + i];
            atomicAdd(&g_upd[(b * 8 + i) * 256 + h * 64 + d], s);
        }
    }
}

// ---------------- GRU cell ----------------
__global__ void gru_kernel(const float* __restrict__ w_ih, const float* __restrict__ w_hh,
                           const float* __restrict__ b_ih, const float* __restrict__ b_hh) {
    __shared__ float us[8][256];
    __shared__ float hs[8][256];
    int rb = blockIdx.x * 8;
    int t = threadIdx.x;
#pragma unroll
    for (int r = 0; r < 8; r++) {
        us[r][t] = g_upd[(rb + r) * 256 + t];
        hs[r][t] = g_slots[(rb + r) * 256 + t];
    }
    __syncthreads();
    float gir[8] = {0}, giz[8] = {0}, gin[8] = {0};
    float ghr[8] = {0}, ghz[8] = {0}, ghn[8] = {0};
    const float* wir = &w_ih[(size_t)t * 256];
    const float* wiz = &w_ih[(size_t)(256 + t) * 256];
    const float* win = &w_ih[(size_t)(512 + t) * 256];
    const float* whr = &w_hh[(size_t)t * 256];
    const float* whz = &w_hh[(size_t)(256 + t) * 256];
    const float* whn = &w_hh[(size_t)(512 + t) * 256];
    for (int cc = 0; cc < 256; cc++) {
        float a = wir[cc], bq = wiz[cc], c = win[cc];
        float d = whr[cc], e = whz[cc], f = whn[cc];
#pragma unroll
        for (int r = 0; r < 8; r++) {
            float u = us[r][cc], hh = hs[r][cc];
            gir[r] += a * u; giz[r] += bq * u; gin[r] += c * u;
            ghr[r] += d * hh; ghz[r] += e * hh; ghn[r] += f * hh;
        }
    }
    float bir = b_ih[t], biz = b_ih[256 + t], bin_ = b_ih[512 + t];
    float bhr = b_hh[t], bhz = b_hh[256 + t], bhn = b_hh[512 + t];
#pragma unroll
    for (int r = 0; r < 8; r++) {
        float rr = sigmoidf_(gir[r] + bir + ghr[r] + bhr);
        float zz = sigmoidf_(giz[r] + biz + ghz[r] + bhz);
        float nn = tanhf(gin[r] + bin_ + rr * (ghn[r] + bhn));
        g_slots[(rb + r) * 256 + t] = (1.0f - zz) * nn + zz * hs[r][t];
    }
}

// ---------------- FFN part 1: LN -> Linear(1024) -> GELU(exact) ----------------
__global__ void ffn1_kernel(const float* __restrict__ w_ff1, const float* __restrict__ b_ff1,
                            const float* __restrict__ lng, const float* __restrict__ lnb) {
    __shared__ float xs[8][256];
    __shared__ float mu8[8], rs8[8];
    int rb = blockIdx.x * 8;
    int t = threadIdx.x, w = t >> 5, lane = t & 31;
    {
        const float* sr = &g_slots[(rb + w) * 256];
        float s = 0.f, s2 = 0.f;
#pragma unroll
        for (int u = 0; u < 8; u++) { float v = sr[lane + u * 32]; s += v; s2 += v * v; }
#pragma unroll
        for (int o = 16; o; o >>= 1) {
            s += __shfl_xor_sync(0xffffffffu, s, o);
            s2 += __shfl_xor_sync(0xffffffffu, s2, o);
        }
        if (lane == 0) {
            float m = s * (1.0f / 256.0f);
            float var = s2 * (1.0f / 256.0f) - m * m;
            mu8[w] = m; rs8[w] = rsqrtf(var + 1e-5f);
        }
    }
    __syncthreads();
    float gg = lng[t], bb = lnb[t];
#pragma unroll
    for (int r = 0; r < 8; r++)
        xs[r][t] = (g_slots[(rb + r) * 256 + t] - mu8[r]) * rs8[r] * gg + bb;
    __syncthreads();
    for (int j4 = 0; j4 < 4; j4++) {
        int j = j4 * 256 + t;
        float acc[8] = {0, 0, 0, 0, 0, 0, 0, 0};
        const float* wr = &w_ff1[(size_t)j * 256];
        for (int cc = 0; cc < 256; cc++) {
            float wv = wr[cc];
#pragma unroll
            for (int r = 0; r < 8; r++) acc[r] += xs[r][cc] * wv;
        }
        float bj = b_ff1[j];
#pragma unroll
        for (int r = 0; r < 8; r++) {
            float x = acc[r] + bj;
            g_ff[(rb + r) * 1024 + j] = 0.5f * x * (1.0f + erff(x * 0.70710678118654752f));
        }
    }
}

// ---------------- FFN part 2: Linear back + residual ----------------
__global__ void ffn2_kernel(const float* __restrict__ w_ff2, const float* __restrict__ b_ff2) {
    __shared__ float fs[8][1024];
    int rb = blockIdx.x * 8;
    int t = threadIdx.x;
#pragma unroll
    for (int u = 0; u < 8; u++) {
        int l = u * 256 + t;
        int r = l >> 8, c4 = l & 255;
        *(float4*)&fs[r][c4 * 4] = *(const float4*)&g_ff[(rb + r) * 1024 + c4 * 4];
    }
    __syncthreads();
    float acc[8] = {0, 0, 0, 0, 0, 0, 0, 0};
    const float* wr = &w_ff2[(size_t)t * 1024];
    for (int jj = 0; jj < 1024; jj++) {
        float wv = wr[jj];
#pragma unroll
        for (int r = 0; r < 8; r++) acc[r] += fs[r][jj] * wv;
    }
    float bc = b_ff2[t];
#pragma unroll
    for (int r = 0; r < 8; r++) g_slots[(rb + r) * 256 + t] += acc[r] + bc;
}

// ---------------- host ----------------
extern "C" void kernel_launch(void* const* d_in, const int* in_sizes, int n_in,
                              void* d_out, int out_size) {
    const float* inputs = (const float*)d_in[0];
    const float* slots0 = (const float*)d_in[1];
    const float* w_q = (const float*)d_in[2];
    const float* w_k = (const float*)d_in[3];
    const float* w_v = (const float*)d_in[4];
    const float* w_ih = (const float*)d_in[5];
    const float* w_hh = (const float*)d_in[6];
    const float* b_ih = (const float*)d_in[7];
    const float* b_hh = (const float*)d_in[8];
    const float* ln_in_g = (const float*)d_in[9];
    const float* ln_in_b = (const float*)d_in[10];
    const float* ln_s_g = (const float*)d_in[11];
    const float* ln_s_b = (const float*)d_in[12];
    const float* ln_ff_g = (const float*)d_in[13];
    const float* ln_ff_b = (const float*)d_in[14];
    const float* w_ff1 = (const float*)d_in[15];
    const float* b_ff1 = (const float*)d_in[16];
    const float* w_ff2 = (const float*)d_in[17];
    const float* b_ff2 = (const float*)d_in[18];
    float* out = (float*)d_out;

    void *slots_dev, *S_dev, *upd_dev;
    cudaGetSymbolAddress(&slots_dev, g_slots);
    cudaGetSymbolAddress(&S_dev, g_S);
    cudaGetSymbolAddress(&upd_dev, g_upd);

    cudaMemcpyAsync(slots_dev, slots0, 128 * 256 * sizeof(float), cudaMemcpyDeviceToDevice);
    prep_fold<<<512, 256>>>(w_k, w_v, ln_in_g, ln_in_b);
    rowstats<<<(Bc * Nc) / 8, 256>>>(inputs);
    kv_gemm<<<dim3(4, (Bc * Nc) / 128), 256>>>(inputs);

    for (int it = 0; it < 3; it++) {
        qproj<<<16, 256>>>(w_q, ln_s_g, ln_s_b);
        cudaMemsetAsync(S_dev, 0, 16 * 32 * sizeof(float));
        dots_kernel<<<dim3(32, 16), 256>>>((it == 2) ? (out + 128 * 256) : (float*)0);
        cudaMemsetAsync(upd_dev, 0, 128 * 256 * sizeof(float));
        upd_kernel<<<dim3(4, 4, 16), 256>>>();
        gru_kernel<<<16, 256>>>(w_ih, w_hh, b_ih, b_hh);
        ffn1_kernel<<<16, 256>>>(w_ff1, b_ff1, ln_ff_g, ln_ff_b);
        ffn2_kernel<<<16, 256>>>(w_ff2, b_ff2);
    }
    cudaMemcpyAsync(d_out, slots_dev, 128 * 256 * sizeof(float), cudaMemcpyDeviceToDevice);
}

// round 3
// speedup vs baseline: 1.2877x; 1.2877x over previous
#include <cuda_runtime.h>
#include <math.h>

#define Bc 16
#define Nc 16384
#define Kc 8
#define DIMc 256
#define Hc 4
#define DHc 64
#define EPSc 1e-8f
#define SCALEc 0.125f

// ---------------- scratch (static device globals; no allocation) ----------------
__device__ float g_k[(size_t)Bc * Nc * DIMc];      // 256 MB
__device__ float g_v[(size_t)Bc * Nc * DIMc];      // 256 MB
__device__ float g_attn[(size_t)Bc * Nc * 32];     // 32 MB  [b][n][i*4+h]
__device__ float g_mu[Bc * Nc];
__device__ float g_rstd[Bc * Nc];
__device__ float g_Wg[512 * 256];                  // folded [k;v] weights * ln_in_g
__device__ float g_s1[512];
__device__ float g_s2[512];
__device__ float g_q[128 * 256];                   // [b*8+i][h*64+d]
__device__ float g_S[16 * 32];                     // attn row sums [b][i*4+h]
__device__ float g_upd[128 * 256];
__device__ float g_slots[128 * 256];
__device__ float g_ff[128 * 1024];

__device__ __forceinline__ float sigmoidf_(float x) { return 1.0f / (1.0f + expf(-x)); }

__device__ __forceinline__ unsigned cvt_tf32(float f) {
    unsigned r;
    asm("cvt.rna.tf32.f32 %0, %1;" : "=r"(r) : "f"(f));
    return r;
}

__device__ __forceinline__ void mma_tf32(float c[4], const unsigned a[4], const unsigned b[2]) {
    asm volatile(
        "mma.sync.aligned.m16n8k8.row.col.f32.tf32.tf32.f32 "
        "{%0,%1,%2,%3},{%4,%5,%6,%7},{%8,%9},{%0,%1,%2,%3};"
        : "+f"(c[0]), "+f"(c[1]), "+f"(c[2]), "+f"(c[3])
        : "r"(a[0]), "r"(a[1]), "r"(a[2]), "r"(a[3]), "r"(b[0]), "r"(b[1]));
}

// ---------------- prep: fold ln_in gamma/beta into K/V weights ----------------
__global__ void prep_fold(const float* __restrict__ wk, const float* __restrict__ wv,
                          const float* __restrict__ g, const float* __restrict__ b) {
    int j = blockIdx.x;           // 0..511
    int c = threadIdx.x;          // 0..255
    const float* W = (j < 256) ? (wk + (size_t)j * 256) : (wv + (size_t)(j - 256) * 256);
    float w = W[c];
    float wg = w * g[c];
    float wb = w * b[c];
    g_Wg[j * 256 + c] = wg;
    __shared__ float r1[8], r2[8];
    float a = wg, bb = wb;
#pragma unroll
    for (int o = 16; o; o >>= 1) {
        a += __shfl_xor_sync(0xffffffffu, a, o);
        bb += __shfl_xor_sync(0xffffffffu, bb, o);
    }
    if ((c & 31) == 0) { r1[c >> 5] = a; r2[c >> 5] = bb; }
    __syncthreads();
    if (c == 0) {
        float s1 = 0.f, s2 = 0.f;
#pragma unroll
        for (int u = 0; u < 8; u++) { s1 += r1[u]; s2 += r2[u]; }
        g_s1[j] = s1; g_s2[j] = s2;
    }
}

// ---------------- row stats of inputs (mean / rstd) ----------------
__global__ void rowstats(const float* __restrict__ x) {
    int row = blockIdx.x * 8 + (threadIdx.x >> 5);
    int lane = threadIdx.x & 31;
    const float* xr = x + (size_t)row * 256;
    float s = 0.f, s2 = 0.f;
#pragma unroll
    for (int u = 0; u < 8; u++) {
        float v = xr[lane + u * 32];
        s += v; s2 += v * v;
    }
#pragma unroll
    for (int o = 16; o; o >>= 1) {
        s += __shfl_xor_sync(0xffffffffu, s, o);
        s2 += __shfl_xor_sync(0xffffffffu, s2, o);
    }
    if (lane == 0) {
        float m = s * (1.0f / 256.0f);
        float var = s2 * (1.0f / 256.0f) - m * m;
        g_mu[row] = m;
        g_rstd[row] = rsqrtf(var + 1e-5f);
    }
}

// ---------------- big GEMM on tensor cores (tf32 mma), LN epilogue ----------------
// C[M,512] = x[M,256] @ Wg^T ; BM=128 BN=128 BK=32 ; 256 thr = 8 warps (4x2)
// warp tile 32(M) x 64(N) = 2 x 8 mma(m16n8k8)
#define GPAD 36
__global__ __launch_bounds__(256) void kv_gemm_tc(const float* __restrict__ x) {
    __shared__ unsigned As[128 * GPAD];   // [m][k] padded
    __shared__ unsigned Bs[128 * GPAD];   // [n][k] padded
    const int tid = threadIdx.x;
    const int wid = tid >> 5, lane = tid & 31;
    const int g = lane >> 2, tig = lane & 3;
    const int wm = (wid & 3) * 32, wn = (wid >> 2) * 64;
    const int bm = blockIdx.y * 128, bn = blockIdx.x * 128;
    const int lrow = tid >> 3;           // 0..31
    const int lc4 = tid & 7;             // 0..7 (float4 column)

    float c[2][8][4];
#pragma unroll
    for (int mt = 0; mt < 2; mt++)
#pragma unroll
        for (int nt = 0; nt < 8; nt++)
#pragma unroll
            for (int e = 0; e < 4; e++) c[mt][nt][e] = 0.f;

    float4 areg[4], breg[4];
    // prefetch first tile (k0 = 0)
#pragma unroll
    for (int u = 0; u < 4; u++) {
        int r = u * 32 + lrow;
        areg[u] = *(const float4*)&x[(size_t)(bm + r) * 256 + lc4 * 4];
        breg[u] = *(const float4*)&g_Wg[(size_t)(bn + r) * 256 + lc4 * 4];
    }

    for (int iter = 0; iter < 8; iter++) {
        // stage current tile to smem with RNA tf32 rounding
#pragma unroll
        for (int u = 0; u < 4; u++) {
            int r = u * 32 + lrow;
            uint4 ta = make_uint4(cvt_tf32(areg[u].x), cvt_tf32(areg[u].y),
                                  cvt_tf32(areg[u].z), cvt_tf32(areg[u].w));
            uint4 tb = make_uint4(cvt_tf32(breg[u].x), cvt_tf32(breg[u].y),
                                  cvt_tf32(breg[u].z), cvt_tf32(breg[u].w));
            *(uint4*)&As[r * GPAD + lc4 * 4] = ta;
            *(uint4*)&Bs[r * GPAD + lc4 * 4] = tb;
        }
        __syncthreads();
        if (iter < 7) {
            int k0 = (iter + 1) * 32;
#pragma unroll
            for (int u = 0; u < 4; u++) {
                int r = u * 32 + lrow;
                areg[u] = *(const float4*)&x[(size_t)(bm + r) * 256 + k0 + lc4 * 4];
                breg[u] = *(const float4*)&g_Wg[(size_t)(bn + r) * 256 + k0 + lc4 * 4];
            }
        }
#pragma unroll
        for (int kk = 0; kk < 32; kk += 8) {
            unsigned af[2][4];
#pragma unroll
            for (int mt = 0; mt < 2; mt++) {
                int mr = wm + mt * 16;
                af[mt][0] = As[(mr + g) * GPAD + kk + tig];
                af[mt][1] = As[(mr + 8 + g) * GPAD + kk + tig];
                af[mt][2] = As[(mr + g) * GPAD + kk + tig + 4];
                af[mt][3] = As[(mr + 8 + g) * GPAD + kk + tig + 4];
            }
            unsigned bf[8][2];
#pragma unroll
            for (int nt = 0; nt < 8; nt++) {
                int nr = wn + nt * 8;
                bf[nt][0] = Bs[(nr + g) * GPAD + kk + tig];
                bf[nt][1] = Bs[(nr + g) * GPAD + kk + tig + 4];
            }
#pragma unroll
            for (int mt = 0; mt < 2; mt++)
#pragma unroll
                for (int nt = 0; nt < 8; nt++) mma_tf32(c[mt][nt], af[mt], bf[nt]);
        }
        __syncthreads();
    }

    // LN epilogue + store
    const bool isk = (bn < 256);
    float* dst = isk ? g_k : g_v;
#pragma unroll
    for (int nt = 0; nt < 8; nt++) {
        int colg = bn + wn + nt * 8 + tig * 2;         // 0..511
        float2 s1v = *(const float2*)&g_s1[colg];
        float2 s2v = *(const float2*)&g_s2[colg];
        int cl = isk ? colg : (colg - 256);
#pragma unroll
        for (int mt = 0; mt < 2; mt++) {
            int r0 = bm + wm + mt * 16 + g;
            float mu0 = g_mu[r0], rs0 = g_rstd[r0];
            float mu1 = g_mu[r0 + 8], rs1 = g_rstd[r0 + 8];
            float2 o0, o1;
            o0.x = rs0 * (c[mt][nt][0] - mu0 * s1v.x) + s2v.x;
            o0.y = rs0 * (c[mt][nt][1] - mu0 * s1v.y) + s2v.y;
            o1.x = rs1 * (c[mt][nt][2] - mu1 * s1v.x) + s2v.x;
            o1.y = rs1 * (c[mt][nt][3] - mu1 * s1v.y) + s2v.y;
            *(float2*)&dst[(size_t)r0 * 256 + cl] = o0;
            *(float2*)&dst[(size_t)(r0 + 8) * 256 + cl] = o1;
        }
    }
}

// ---------------- q projection: q = LN(slots; ln_s) @ w_q^T ----------------
__global__ void qproj(const float* __restrict__ wq, const float* __restrict__ lng,
                      const float* __restrict__ lnb) {
    __shared__ float xs[8][256];
    __shared__ float mu8[8], rs8[8];
    int rb = blockIdx.x * 8;
    int t = threadIdx.x, w = t >> 5, lane = t & 31;
    {
        const float* sr = &g_slots[(rb + w) * 256];
        float s = 0.f, s2 = 0.f;
#pragma unroll
        for (int u = 0; u < 8; u++) { float v = sr[lane + u * 32]; s += v; s2 += v * v; }
#pragma unroll
        for (int o = 16; o; o >>= 1) {
            s += __shfl_xor_sync(0xffffffffu, s, o);
            s2 += __shfl_xor_sync(0xffffffffu, s2, o);
        }
        if (lane == 0) {
            float m = s * (1.0f / 256.0f);
            float var = s2 * (1.0f / 256.0f) - m * m;
            mu8[w] = m; rs8[w] = rsqrtf(var + 1e-5f);
        }
    }
    __syncthreads();
    float gg = lng[t], bb = lnb[t];
#pragma unroll
    for (int r = 0; r < 8; r++)
        xs[r][t] = (g_slots[(rb + r) * 256 + t] - mu8[r]) * rs8[r] * gg + bb;
    __syncthreads();
    float acc[8] = {0, 0, 0, 0, 0, 0, 0, 0};
    const float* wr = &wq[(size_t)t * 256];
    for (int cc = 0; cc < 256; cc++) {
        float wv = wr[cc];
#pragma unroll
        for (int r = 0; r < 8; r++) acc[r] += xs[r][cc] * wv;
    }
#pragma unroll
    for (int r = 0; r < 8; r++) g_q[(rb + r) * 256 + t] = acc[r];
}

// ---------------- dots + inverted softmax + attn_out + row sums ----------------
__global__ void dots_kernel(float* __restrict__ ao) {
    __shared__ float ks[32][260];
    __shared__ float qs[8][260];
    __shared__ float sred[32][33];
    int b = blockIdx.y;
    int n0 = blockIdx.x * 512;
    int t = threadIdx.x;
#pragma unroll
    for (int u = 0; u < 2; u++) {
        int l = u * 256 + t;
        int i = l >> 6, c4 = l & 63;
        *(float4*)&qs[i][c4 * 4] = *(const float4*)&g_q[(b * 8 + i) * 256 + c4 * 4];
    }
    int n_l = t >> 3, i = t & 7;
    float sacc[4] = {0, 0, 0, 0};
    for (int tile = 0; tile < 16; tile++) {
        int nt = n0 + tile * 32;
        __syncthreads();
#pragma unroll
        for (int u = 0; u < 8; u++) {
            int l = u * 256 + t;
            int r = l >> 6, c4 = l & 63;
            *(float4*)&ks[r][c4 * 4] =
                *(const float4*)&g_k[((size_t)b * Nc + nt + r) * 256 + c4 * 4];
        }
        __syncthreads();
        float dot[4] = {0, 0, 0, 0};
#pragma unroll
        for (int d4 = 0; d4 < 64; d4++) {
            float4 kk = *(float4*)&ks[n_l][d4 * 4];
            float4 qq = *(float4*)&qs[i][d4 * 4];
            int h = d4 >> 4;
            dot[h] += kk.x * qq.x + kk.y * qq.y + kk.z * qq.z + kk.w * qq.w;
        }
#pragma unroll
        for (int h = 0; h < 4; h++) dot[h] *= SCALEc;
        float m = fmaxf(fmaxf(dot[0], dot[1]), fmaxf(dot[2], dot[3]));
#pragma unroll
        for (int o = 1; o < 8; o <<= 1) m = fmaxf(m, __shfl_xor_sync(0xffffffffu, m, o));
        float e0 = __expf(dot[0] - m), e1 = __expf(dot[1] - m);
        float e2 = __expf(dot[2] - m), e3 = __expf(dot[3] - m);
        float s = e0 + e1 + e2 + e3;
#pragma unroll
        for (int o = 1; o < 8; o <<= 1) s += __shfl_xor_sync(0xffffffffu, s, o);
        float inv = 1.0f / s;
        float4 av = make_float4(e0 * inv, e1 * inv, e2 * inv, e3 * inv);
        int n = nt + n_l;
        *(float4*)&g_attn[((size_t)b * Nc + n) * 32 + i * 4] = av;
        sacc[0] += av.x; sacc[1] += av.y; sacc[2] += av.z; sacc[3] += av.w;
        if (ao) ao[(size_t)(b * 8 + i) * Nc + n] = (av.x + av.y + av.z + av.w) * 0.25f;
    }
    sred[n_l][i * 4 + 0] = sacc[0];
    sred[n_l][i * 4 + 1] = sacc[1];
    sred[n_l][i * 4 + 2] = sacc[2];
    sred[n_l][i * 4 + 3] = sacc[3];
    __syncthreads();
    if (t < 32) {
        float s = 0.f;
#pragma unroll
        for (int nl = 0; nl < 32; nl++) s += sred[nl][t];
        atomicAdd(&g_S[b * 32 + t], s);
    }
}

// ---------------- updates: upd[b,i,h,d] = sum_n attnN * v ----------------
__global__ void upd_kernel() {
    __shared__ float vt[64][68];
    __shared__ float at[64][8];
    __shared__ float ivs[8];
    int b = blockIdx.z, h = blockIdx.y, ch = blockIdx.x;
    int t = threadIdx.x;
    int d = t & 63, sub = t >> 6;
    if (t < 8) ivs[t] = 1.0f / (g_S[b * 32 + t * 4 + h] + EPSc);
    __syncthreads();
    float acc[8] = {0, 0, 0, 0, 0, 0, 0, 0};
    for (int tile = 0; tile < 64; tile++) {
        int nt = ch * 4096 + tile * 64;
        __syncthreads();
#pragma unroll
        for (int u = 0; u < 4; u++) {
            int l = u * 256 + t;
            int r = l >> 4, c4 = l & 15;
            *(float4*)&vt[r][c4 * 4] =
                *(const float4*)&g_v[((size_t)b * Nc + nt + r) * 256 + h * 64 + c4 * 4];
        }
#pragma unroll
        for (int u = 0; u < 2; u++) {
            int l = u * 256 + t;
            int r = l >> 3, ii = l & 7;
            float raw = g_attn[((size_t)b * Nc + nt + r) * 32 + ii * 4 + h];
            at[r][ii] = (raw + EPSc) * ivs[ii];
        }
        __syncthreads();
#pragma unroll
        for (int nn = 0; nn < 16; nn++) {
            int nl = nn * 4 + sub;
            float vv = vt[nl][d];
            float4 a0 = *(float4*)&at[nl][0];
            float4 a1 = *(float4*)&at[nl][4];
            acc[0] += a0.x * vv; acc[1] += a0.y * vv;
            acc[2] += a0.z * vv; acc[3] += a0.w * vv;
            acc[4] += a1.x * vv; acc[5] += a1.y * vv;
            acc[6] += a1.z * vv; acc[7] += a1.w * vv;
        }
    }
    __syncthreads();
    float* red = &vt[0][0];
#pragma unroll
    for (int i = 0; i < 8; i++) red[(sub * 64 + d) * 8 + i] = acc[i];
    __syncthreads();
    if (sub == 0) {
#pragma unroll
        for (int i = 0; i < 8; i++) {
            float s = red[(0 * 64 + d) * 8 + i] + red[(1 * 64 + d) * 8 + i] +
                      red[(2 * 64 + d) * 8 + i] + red[(3 * 64 + d) * 8 + i];
            atomicAdd(&g_upd[(b * 8 + i) * 256 + h * 64 + d], s);
        }
    }
}

// ---------------- GRU cell ----------------
__global__ void gru_kernel(const float* __restrict__ w_ih, const float* __restrict__ w_hh,
                           const float* __restrict__ b_ih, const float* __restrict__ b_hh) {
    __shared__ float us[8][256];
    __shared__ float hs[8][256];
    int rb = blockIdx.x * 8;
    int t = threadIdx.x;
#pragma unroll
    for (int r = 0; r < 8; r++) {
        us[r][t] = g_upd[(rb + r) * 256 + t];
        hs[r][t] = g_slots[(rb + r) * 256 + t];
    }
    __syncthreads();
    float gir[8] = {0}, giz[8] = {0}, gin[8] = {0};
    float ghr[8] = {0}, ghz[8] = {0}, ghn[8] = {0};
    const float* wir = &w_ih[(size_t)t * 256];
    const float* wiz = &w_ih[(size_t)(256 + t) * 256];
    const float* win = &w_ih[(size_t)(512 + t) * 256];
    const float* whr = &w_hh[(size_t)t * 256];
    const float* whz = &w_hh[(size_t)(256 + t) * 256];
    const float* whn = &w_hh[(size_t)(512 + t) * 256];
    for (int cc = 0; cc < 256; cc++) {
        float a = wir[cc], bq = wiz[cc], c = win[cc];
        float d = whr[cc], e = whz[cc], f = whn[cc];
#pragma unroll
        for (int r = 0; r < 8; r++) {
            float u = us[r][cc], hh = hs[r][cc];
            gir[r] += a * u; giz[r] += bq * u; gin[r] += c * u;
            ghr[r] += d * hh; ghz[r] += e * hh; ghn[r] += f * hh;
        }
    }
    float bir = b_ih[t], biz = b_ih[256 + t], bin_ = b_ih[512 + t];
    float bhr = b_hh[t], bhz = b_hh[256 + t], bhn = b_hh[512 + t];
#pragma unroll
    for (int r = 0; r < 8; r++) {
        float rr = sigmoidf_(gir[r] + bir + ghr[r] + bhr);
        float zz = sigmoidf_(giz[r] + biz + ghz[r] + bhz);
        float nn = tanhf(gin[r] + bin_ + rr * (ghn[r] + bhn));
        g_slots[(rb + r) * 256 + t] = (1.0f - zz) * nn + zz * hs[r][t];
    }
}

// ---------------- FFN part 1: LN -> Linear(1024) -> GELU(exact) ----------------
__global__ void ffn1_kernel(const float* __restrict__ w_ff1, const float* __restrict__ b_ff1,
                            const float* __restrict__ lng, const float* __restrict__ lnb) {
    __shared__ float xs[8][256];
    __shared__ float mu8[8], rs8[8];
    int rb = blockIdx.x * 8;
    int t = threadIdx.x, w = t >> 5, lane = t & 31;
    {
        const float* sr = &g_slots[(rb + w) * 256];
        float s = 0.f, s2 = 0.f;
#pragma unroll
        for (int u = 0; u < 8; u++) { float v = sr[lane + u * 32]; s += v; s2 += v * v; }
#pragma unroll
        for (int o = 16; o; o >>= 1) {
            s += __shfl_xor_sync(0xffffffffu, s, o);
            s2 += __shfl_xor_sync(0xffffffffu, s2, o);
        }
        if (lane == 0) {
            float m = s * (1.0f / 256.0f);
            float var = s2 * (1.0f / 256.0f) - m * m;
            mu8[w] = m; rs8[w] = rsqrtf(var + 1e-5f);
        }
    }
    __syncthreads();
    float gg = lng[t], bb = lnb[t];
#pragma unroll
    for (int r = 0; r < 8; r++)
        xs[r][t] = (g_slots[(rb + r) * 256 + t] - mu8[r]) * rs8[r] * gg + bb;
    __syncthreads();
    for (int j4 = 0; j4 < 4; j4++) {
        int j = j4 * 256 + t;
        float acc[8] = {0, 0, 0, 0, 0, 0, 0, 0};
        const float* wr = &w_ff1[(size_t)j * 256];
        for (int cc = 0; cc < 256; cc++) {
            float wv = wr[cc];
#pragma unroll
            for (int r = 0; r < 8; r++) acc[r] += xs[r][cc] * wv;
        }
        float bj = b_ff1[j];
#pragma unroll
        for (int r = 0; r < 8; r++) {
            float x = acc[r] + bj;
            g_ff[(rb + r) * 1024 + j] = 0.5f * x * (1.0f + erff(x * 0.70710678118654752f));
        }
    }
}

// ---------------- FFN part 2: Linear back + residual ----------------
__global__ void ffn2_kernel(const float* __restrict__ w_ff2, const float* __restrict__ b_ff2) {
    __shared__ float fs[8][1024];
    int rb = blockIdx.x * 8;
    int t = threadIdx.x;
#pragma unroll
    for (int u = 0; u < 8; u++) {
        int l = u * 256 + t;
        int r = l >> 8, c4 = l & 255;
        *(float4*)&fs[r][c4 * 4] = *(const float4*)&g_ff[(rb + r) * 1024 + c4 * 4];
    }
    __syncthreads();
    float acc[8] = {0, 0, 0, 0, 0, 0, 0, 0};
    const float* wr = &w_ff2[(size_t)t * 1024];
    for (int jj = 0; jj < 1024; jj++) {
        float wv = wr[jj];
#pragma unroll
        for (int r = 0; r < 8; r++) acc[r] += fs[r][jj] * wv;
    }
    float bc = b_ff2[t];
#pragma unroll
    for (int r = 0; r < 8; r++) g_slots[(rb + r) * 256 + t] += acc[r] + bc;
}

// ---------------- host ----------------
extern "C" void kernel_launch(void* const* d_in, const int* in_sizes, int n_in,
                              void* d_out, int out_size) {
    const float* inputs = (const float*)d_in[0];
    const float* slots0 = (const float*)d_in[1];
    const float* w_q = (const float*)d_in[2];
    const float* w_k = (const float*)d_in[3];
    const float* w_v = (const float*)d_in[4];
    const float* w_ih = (const float*)d_in[5];
    const float* w_hh = (const float*)d_in[6];
    const float* b_ih = (const float*)d_in[7];
    const float* b_hh = (const float*)d_in[8];
    const float* ln_in_g = (const float*)d_in[9];
    const float* ln_in_b = (const float*)d_in[10];
    const float* ln_s_g = (const float*)d_in[11];
    const float* ln_s_b = (const float*)d_in[12];
    const float* ln_ff_g = (const float*)d_in[13];
    const float* ln_ff_b = (const float*)d_in[14];
    const float* w_ff1 = (const float*)d_in[15];
    const float* b_ff1 = (const float*)d_in[16];
    const float* w_ff2 = (const float*)d_in[17];
    const float* b_ff2 = (const float*)d_in[18];
    float* out = (float*)d_out;

    void *slots_dev, *S_dev, *upd_dev;
    cudaGetSymbolAddress(&slots_dev, g_slots);
    cudaGetSymbolAddress(&S_dev, g_S);
    cudaGetSymbolAddress(&upd_dev, g_upd);

    cudaMemcpyAsync(slots_dev, slots0, 128 * 256 * sizeof(float), cudaMemcpyDeviceToDevice);
    prep_fold<<<512, 256>>>(w_k, w_v, ln_in_g, ln_in_b);
    rowstats<<<(Bc * Nc) / 8, 256>>>(inputs);
    kv_gemm_tc<<<dim3(4, (Bc * Nc) / 128), 256>>>(inputs);

    for (int it = 0; it < 3; it++) {
        qproj<<<16, 256>>>(w_q, ln_s_g, ln_s_b);
        cudaMemsetAsync(S_dev, 0, 16 * 32 * sizeof(float));
        dots_kernel<<<dim3(32, 16), 256>>>((it == 2) ? (out + 128 * 256) : (float*)0);
        cudaMemsetAsync(upd_dev, 0, 128 * 256 * sizeof(float));
        upd_kernel<<<dim3(4, 4, 16), 256>>>();
        gru_kernel<<<16, 256>>>(w_ih, w_hh, b_ih, b_hh);
        ffn1_kernel<<<16, 256>>>(w_ff1, b_ff1, ln_ff_g, ln_ff_b);
        ffn2_kernel<<<16, 256>>>(w_ff2, b_ff2);
    }
    cudaMemcpyAsync(d_out, slots_dev, 128 * 256 * sizeof(float), cudaMemcpyDeviceToDevice);
}

// round 4
// speedup vs baseline: 2.6905x; 2.0894x over previous
#include <cuda_runtime.h>
#include <math.h>

#define Bc 16
#define Nc 16384
#define Kc 8
#define DIMc 256
#define Hc 4
#define DHc 64
#define EPSc 1e-8f
#define SCALEc 0.125f

// ---------------- scratch (static device globals; no allocation) ----------------
__device__ float g_k[(size_t)Bc * Nc * DIMc];      // 256 MB
__device__ float g_v[(size_t)Bc * Nc * DIMc];      // 256 MB
__device__ float g_attn[(size_t)Bc * Nc * 32];     // 32 MB  [b][n][i*4+h]
__device__ float g_Wg[512 * 256];                  // folded [k;v] weights * ln_in_g
__device__ float g_s1[512];
__device__ float g_s2[512];
__device__ float g_q[128 * 256];                   // [b*8+i][h*64+d]
__device__ float g_S[16 * 32];                     // attn row sums [b][i*4+h]
__device__ float g_upd[128 * 256];
__device__ float g_slots[128 * 256];
__device__ float g_ff[128 * 1024];
__device__ float g_x[128 * 256];                   // LN staging
__device__ float g_gi[128 * 768];
__device__ float g_gh[128 * 768];

__device__ __forceinline__ float sigmoidf_(float x) { return 1.0f / (1.0f + expf(-x)); }
__device__ __forceinline__ float geluf_(float x) {
    return 0.5f * x * (1.0f + erff(x * 0.70710678118654752f));
}

__device__ __forceinline__ unsigned cvt_tf32(float f) {
    unsigned r;
    asm("cvt.rna.tf32.f32 %0, %1;" : "=r"(r) : "f"(f));
    return r;
}

__device__ __forceinline__ void mma_tf32(float c[4], const unsigned a[4], const unsigned b[2]) {
    asm volatile(
        "mma.sync.aligned.m16n8k8.row.col.f32.tf32.tf32.f32 "
        "{%0,%1,%2,%3},{%4,%5,%6,%7},{%8,%9},{%0,%1,%2,%3};"
        : "+f"(c[0]), "+f"(c[1]), "+f"(c[2]), "+f"(c[3])
        : "r"(a[0]), "r"(a[1]), "r"(a[2]), "r"(a[3]), "r"(b[0]), "r"(b[1]));
}

// ---------------- prep: fold ln_in gamma/beta into K/V weights ----------------
__global__ void prep_fold(const float* __restrict__ wk, const float* __restrict__ wv,
                          const float* __restrict__ g, const float* __restrict__ b) {
    int j = blockIdx.x;           // 0..511
    int c = threadIdx.x;          // 0..255
    const float* W = (j < 256) ? (wk + (size_t)j * 256) : (wv + (size_t)(j - 256) * 256);
    float w = W[c];
    float wg = w * g[c];
    float wb = w * b[c];
    g_Wg[j * 256 + c] = wg;
    __shared__ float r1[8], r2[8];
    float a = wg, bb = wb;
#pragma unroll
    for (int o = 16; o; o >>= 1) {
        a += __shfl_xor_sync(0xffffffffu, a, o);
        bb += __shfl_xor_sync(0xffffffffu, bb, o);
    }
    if ((c & 31) == 0) { r1[c >> 5] = a; r2[c >> 5] = bb; }
    __syncthreads();
    if (c == 0) {
        float s1 = 0.f, s2 = 0.f;
#pragma unroll
        for (int u = 0; u < 8; u++) { s1 += r1[u]; s2 += r2[u]; }
        g_s1[j] = s1; g_s2[j] = s2;
    }
}

// ---------------- big GEMM on tensor cores (tf32 mma), fused rowstats + LN epilogue ----
// C[M,512] = x[M,256] @ Wg^T ; BM=128 BN=128 BK=32 ; 256 thr = 8 warps (4x2)
#define GPAD 36
__global__ __launch_bounds__(256) void kv_gemm_tc(const float* __restrict__ x) {
    __shared__ unsigned As[128 * GPAD];   // [m][k] padded
    __shared__ unsigned Bs[128 * GPAD];   // [n][k] padded
    __shared__ float mu_s[128], rs_s[128];
    const int tid = threadIdx.x;
    const int wid = tid >> 5, lane = tid & 31;
    const int g = lane >> 2, tig = lane & 3;
    const int wm = (wid & 3) * 32, wn = (wid >> 2) * 64;
    const int bm = blockIdx.y * 128, bn = blockIdx.x * 128;
    const int lrow = tid >> 3;           // 0..31
    const int lc4 = tid & 7;             // 0..7 (float4 column)

    float c[2][8][4];
#pragma unroll
    for (int mt = 0; mt < 2; mt++)
#pragma unroll
        for (int nt = 0; nt < 8; nt++)
#pragma unroll
            for (int e = 0; e < 4; e++) c[mt][nt][e] = 0.f;

    float ss[4] = {0, 0, 0, 0}, ss2[4] = {0, 0, 0, 0};

    float4 areg[4], breg[4];
#pragma unroll
    for (int u = 0; u < 4; u++) {
        int r = u * 32 + lrow;
        areg[u] = *(const float4*)&x[(size_t)(bm + r) * 256 + lc4 * 4];
        breg[u] = *(const float4*)&g_Wg[(size_t)(bn + r) * 256 + lc4 * 4];
    }

    for (int iter = 0; iter < 8; iter++) {
#pragma unroll
        for (int u = 0; u < 4; u++) {
            int r = u * 32 + lrow;
            float4 a = areg[u];
            ss[u] += a.x + a.y + a.z + a.w;
            ss2[u] += a.x * a.x + a.y * a.y + a.z * a.z + a.w * a.w;
            uint4 ta = make_uint4(cvt_tf32(a.x), cvt_tf32(a.y), cvt_tf32(a.z), cvt_tf32(a.w));
            uint4 tb = make_uint4(cvt_tf32(breg[u].x), cvt_tf32(breg[u].y),
                                  cvt_tf32(breg[u].z), cvt_tf32(breg[u].w));
            *(uint4*)&As[r * GPAD + lc4 * 4] = ta;
            *(uint4*)&Bs[r * GPAD + lc4 * 4] = tb;
        }
        __syncthreads();
        if (iter < 7) {
            int k0 = (iter + 1) * 32;
#pragma unroll
            for (int u = 0; u < 4; u++) {
                int r = u * 32 + lrow;
                areg[u] = *(const float4*)&x[(size_t)(bm + r) * 256 + k0 + lc4 * 4];
                breg[u] = *(const float4*)&g_Wg[(size_t)(bn + r) * 256 + k0 + lc4 * 4];
            }
        }
#pragma unroll
        for (int kk = 0; kk < 32; kk += 8) {
            unsigned af[2][4];
#pragma unroll
            for (int mt = 0; mt < 2; mt++) {
                int mr = wm + mt * 16;
                af[mt][0] = As[(mr + g) * GPAD + kk + tig];
                af[mt][1] = As[(mr + 8 + g) * GPAD + kk + tig];
                af[mt][2] = As[(mr + g) * GPAD + kk + tig + 4];
                af[mt][3] = As[(mr + 8 + g) * GPAD + kk + tig + 4];
            }
            unsigned bf[8][2];
#pragma unroll
            for (int nt = 0; nt < 8; nt++) {
                int nr = wn + nt * 8;
                bf[nt][0] = Bs[(nr + g) * GPAD + kk + tig];
                bf[nt][1] = Bs[(nr + g) * GPAD + kk + tig + 4];
            }
#pragma unroll
            for (int mt = 0; mt < 2; mt++)
#pragma unroll
                for (int nt = 0; nt < 8; nt++) mma_tf32(c[mt][nt], af[mt], bf[nt]);
        }
        __syncthreads();
    }

    // finalize row stats (reduce over the 8 lanes sharing lrow)
#pragma unroll
    for (int o = 1; o < 8; o <<= 1) {
#pragma unroll
        for (int u = 0; u < 4; u++) {
            ss[u] += __shfl_xor_sync(0xffffffffu, ss[u], o);
            ss2[u] += __shfl_xor_sync(0xffffffffu, ss2[u], o);
        }
    }
    if (lc4 == 0) {
#pragma unroll
        for (int u = 0; u < 4; u++) {
            float m = ss[u] * (1.0f / 256.0f);
            float var = ss2[u] * (1.0f / 256.0f) - m * m;
            mu_s[u * 32 + lrow] = m;
            rs_s[u * 32 + lrow] = rsqrtf(var + 1e-5f);
        }
    }
    __syncthreads();

    // LN epilogue + store
    const bool isk = (bn < 256);
    float* dst = isk ? g_k : g_v;
#pragma unroll
    for (int nt = 0; nt < 8; nt++) {
        int colg = bn + wn + nt * 8 + tig * 2;         // 0..511
        float2 s1v = *(const float2*)&g_s1[colg];
        float2 s2v = *(const float2*)&g_s2[colg];
        int cl = isk ? colg : (colg - 256);
#pragma unroll
        for (int mt = 0; mt < 2; mt++) {
            int lr0 = wm + mt * 16 + g;
            int r0 = bm + lr0;
            float mu0 = mu_s[lr0], rs0 = rs_s[lr0];
            float mu1 = mu_s[lr0 + 8], rs1 = rs_s[lr0 + 8];
            float2 o0, o1;
            o0.x = rs0 * (c[mt][nt][0] - mu0 * s1v.x) + s2v.x;
            o0.y = rs0 * (c[mt][nt][1] - mu0 * s1v.y) + s2v.y;
            o1.x = rs1 * (c[mt][nt][2] - mu1 * s1v.x) + s2v.x;
            o1.y = rs1 * (c[mt][nt][3] - mu1 * s1v.y) + s2v.y;
            *(float2*)&dst[(size_t)r0 * 256 + cl] = o0;
            *(float2*)&dst[(size_t)(r0 + 8) * 256 + cl] = o1;
        }
    }
}

// ---------------- LN over 128 rows of 256 (fp32) ----------------
__global__ void ln_rows(const float* __restrict__ in, const float* __restrict__ g,
                        const float* __restrict__ b, float* __restrict__ outp) {
    int row = blockIdx.x;
    int lane = threadIdx.x;
    const float* xr = &in[row * 256];
    float v[8];
    float s = 0.f, s2 = 0.f;
#pragma unroll
    for (int u = 0; u < 8; u++) {
        v[u] = xr[lane + u * 32];
        s += v[u]; s2 += v[u] * v[u];
    }
#pragma unroll
    for (int o = 16; o; o >>= 1) {
        s += __shfl_xor_sync(0xffffffffu, s, o);
        s2 += __shfl_xor_sync(0xffffffffu, s2, o);
    }
    float m = s * (1.0f / 256.0f);
    float var = s2 * (1.0f / 256.0f) - m * m;
    float rs = rsqrtf(var + 1e-5f);
#pragma unroll
    for (int u = 0; u < 8; u++) {
        int cc = lane + u * 32;
        outp[row * 256 + cc] = (v[u] - m) * rs * g[cc] + b[cc];
    }
}

// ---------------- generic skinny GEMM: out[128,N] = act(X[128,K] @ W[N,K]^T + b) ------
// grid.x = N/2 blocks; 128 threads = 4 warps x 32 rows; lanes split K.
// MODE: 0 = plain, 1 = gelu, 2 = residual add (out = resid + v)
template<int K, int MODE>
__global__ __launch_bounds__(128) void colgemm(const float* __restrict__ X,
                                               const float* __restrict__ W,
                                               const float* __restrict__ bias,
                                               float* __restrict__ out, int ostride,
                                               const float* __restrict__ resid) {
    constexpr int KL = K / 32;                 // floats per lane
    constexpr int RPB = (K == 256) ? 4 : 2;    // rows per batch
    const int j0 = blockIdx.x * 2;
    const int w = threadIdx.x >> 5, lane = threadIdx.x & 31;

    float wf0[KL], wf1[KL];
    const float* w0p = &W[(size_t)j0 * K + lane * KL];
    const float* w1p = &W[(size_t)(j0 + 1) * K + lane * KL];
#pragma unroll
    for (int u = 0; u < KL; u += 4) {
        *(float4*)&wf0[u] = *(const float4*)&w0p[u];
        *(float4*)&wf1[u] = *(const float4*)&w1p[u];
    }
    float b0 = 0.f, b1 = 0.f;
    if (bias) { b0 = bias[j0]; b1 = bias[j0 + 1]; }

    for (int r0 = w * 32; r0 < w * 32 + 32; r0 += RPB) {
        float xf[RPB][KL];
#pragma unroll
        for (int rr = 0; rr < RPB; rr++)
#pragma unroll
            for (int u = 0; u < KL; u += 4)
                *(float4*)&xf[rr][u] =
                    *(const float4*)&X[(size_t)(r0 + rr) * K + lane * KL + u];
        float a0[RPB], a1[RPB];
#pragma unroll
        for (int rr = 0; rr < RPB; rr++) {
            a0[rr] = 0.f; a1[rr] = 0.f;
#pragma unroll
            for (int u = 0; u < KL; u++) {
                a0[rr] += xf[rr][u] * wf0[u];
                a1[rr] += xf[rr][u] * wf1[u];
            }
        }
#pragma unroll
        for (int o = 16; o; o >>= 1)
#pragma unroll
            for (int rr = 0; rr < RPB; rr++) {
                a0[rr] += __shfl_xor_sync(0xffffffffu, a0[rr], o);
                a1[rr] += __shfl_xor_sync(0xffffffffu, a1[rr], o);
            }
        if (lane == 0) {
#pragma unroll
            for (int rr = 0; rr < RPB; rr++) {
                int row = r0 + rr;
                float v0 = a0[rr] + b0, v1 = a1[rr] + b1;
                if (MODE == 1) { v0 = geluf_(v0); v1 = geluf_(v1); }
                if (MODE == 2) {
                    v0 += resid[(size_t)row * ostride + j0];
                    v1 += resid[(size_t)row * ostride + j0 + 1];
                }
                out[(size_t)row * ostride + j0] = v0;
                out[(size_t)row * ostride + j0 + 1] = v1;
            }
        }
    }
}

// ---------------- GRU combine (elementwise) ----------------
__global__ void gru_combine() {
    int row = blockIdx.x;
    int j = threadIdx.x;
    float gir = g_gi[row * 768 + j], giz = g_gi[row * 768 + 256 + j],
          gin = g_gi[row * 768 + 512 + j];
    float ghr = g_gh[row * 768 + j], ghz = g_gh[row * 768 + 256 + j],
          ghn = g_gh[row * 768 + 512 + j];
    float h = g_slots[row * 256 + j];
    float r = sigmoidf_(gir + ghr);
    float z = sigmoidf_(giz + ghz);
    float n = tanhf(gin + r * ghn);
    g_slots[row * 256 + j] = (1.0f - z) * n + z * h;
}

// ---------------- dots + inverted softmax + attn_out + row sums ----------------
// 128 threads; thread = (ng 0..15 -> 2 n rows, i 0..7); tile = 32 n; 16 tiles = 512 n/block
__global__ __launch_bounds__(128) void dots_kernel(float* __restrict__ ao) {
    __shared__ float ks[32][260];
    __shared__ float qs[8][260];
    __shared__ float sred[16][33];
    int b = blockIdx.y;
    int n0 = blockIdx.x * 512;
    int t = threadIdx.x;
#pragma unroll
    for (int u = 0; u < 4; u++) {
        int l = u * 128 + t;
        int i = l >> 6, c4 = l & 63;
        *(float4*)&qs[i][c4 * 4] = *(const float4*)&g_q[(b * 8 + i) * 256 + c4 * 4];
    }
    int ng = t >> 3, i = t & 7;
    float sacc[2][4] = {{0, 0, 0, 0}, {0, 0, 0, 0}};
    for (int tile = 0; tile < 16; tile++) {
        int nt = n0 + tile * 32;
        __syncthreads();
#pragma unroll
        for (int u = 0; u < 16; u++) {
            int l = u * 128 + t;
            int r = l >> 6, c4 = l & 63;
            *(float4*)&ks[r][c4 * 4] =
                *(const float4*)&g_k[((size_t)b * Nc + nt + r) * 256 + c4 * 4];
        }
        __syncthreads();
        float dot[2][4] = {{0, 0, 0, 0}, {0, 0, 0, 0}};
#pragma unroll
        for (int d4 = 0; d4 < 64; d4++) {
            float4 k0 = *(float4*)&ks[ng * 2][d4 * 4];
            float4 k1 = *(float4*)&ks[ng * 2 + 1][d4 * 4];
            float4 qq = *(float4*)&qs[i][d4 * 4];
            int h = d4 >> 4;
            dot[0][h] += k0.x * qq.x + k0.y * qq.y + k0.z * qq.z + k0.w * qq.w;
            dot[1][h] += k1.x * qq.x + k1.y * qq.y + k1.z * qq.z + k1.w * qq.w;
        }
#pragma unroll
        for (int nn = 0; nn < 2; nn++) {
            float d0 = dot[nn][0] * SCALEc, d1 = dot[nn][1] * SCALEc;
            float d2 = dot[nn][2] * SCALEc, d3 = dot[nn][3] * SCALEc;
            float m = fmaxf(fmaxf(d0, d1), fmaxf(d2, d3));
#pragma unroll
            for (int o = 1; o < 8; o <<= 1) m = fmaxf(m, __shfl_xor_sync(0xffffffffu, m, o));
            float e0 = __expf(d0 - m), e1 = __expf(d1 - m);
            float e2 = __expf(d2 - m), e3 = __expf(d3 - m);
            float s = e0 + e1 + e2 + e3;
#pragma unroll
            for (int o = 1; o < 8; o <<= 1) s += __shfl_xor_sync(0xffffffffu, s, o);
            float inv = 1.0f / s;
            float4 av = make_float4(e0 * inv, e1 * inv, e2 * inv, e3 * inv);
            int n = nt + ng * 2 + nn;
            *(float4*)&g_attn[((size_t)b * Nc + n) * 32 + i * 4] = av;
            sacc[nn][0] += av.x; sacc[nn][1] += av.y;
            sacc[nn][2] += av.z; sacc[nn][3] += av.w;
            if (ao) ao[(size_t)(b * 8 + i) * Nc + n] = (av.x + av.y + av.z + av.w) * 0.25f;
        }
    }
#pragma unroll
    for (int h = 0; h < 4; h++) sred[ng][i * 4 + h] = sacc[0][h] + sacc[1][h];
    __syncthreads();
    if (t < 32) {
        float s = 0.f;
#pragma unroll
        for (int nl = 0; nl < 16; nl++) s += sred[nl][t];
        atomicAdd(&g_S[b * 32 + t], s);
    }
}

// ---------------- updates: upd[b,i,h,d] = sum_n attnN * v ----------------
__global__ void upd_kernel() {
    __shared__ float vt[64][68];
    __shared__ float at[64][8];
    __shared__ float ivs[8];
    int b = blockIdx.z, h = blockIdx.y, ch = blockIdx.x;
    int t = threadIdx.x;
    int d = t & 63, sub = t >> 6;
    if (t < 8) ivs[t] = 1.0f / (g_S[b * 32 + t * 4 + h] + EPSc);
    __syncthreads();
    float acc[8] = {0, 0, 0, 0, 0, 0, 0, 0};
    for (int tile = 0; tile < 64; tile++) {
        int nt = ch * 4096 + tile * 64;
        __syncthreads();
#pragma unroll
        for (int u = 0; u < 4; u++) {
            int l = u * 256 + t;
            int r = l >> 4, c4 = l & 15;
            *(float4*)&vt[r][c4 * 4] =
                *(const float4*)&g_v[((size_t)b * Nc + nt + r) * 256 + h * 64 + c4 * 4];
        }
#pragma unroll
        for (int u = 0; u < 2; u++) {
            int l = u * 256 + t;
            int r = l >> 3, ii = l & 7;
            float raw = g_attn[((size_t)b * Nc + nt + r) * 32 + ii * 4 + h];
            at[r][ii] = (raw + EPSc) * ivs[ii];
        }
        __syncthreads();
#pragma unroll
        for (int nn = 0; nn < 16; nn++) {
            int nl = nn * 4 + sub;
            float vv = vt[nl][d];
            float4 a0 = *(float4*)&at[nl][0];
            float4 a1 = *(float4*)&at[nl][4];
            acc[0] += a0.x * vv; acc[1] += a0.y * vv;
            acc[2] += a0.z * vv; acc[3] += a0.w * vv;
            acc[4] += a1.x * vv; acc[5] += a1.y * vv;
            acc[6] += a1.z * vv; acc[7] += a1.w * vv;
        }
    }
    __syncthreads();
    float* red = &vt[0][0];
#pragma unroll
    for (int i = 0; i < 8; i++) red[(sub * 64 + d) * 8 + i] = acc[i];
    __syncthreads();
    if (sub == 0) {
#pragma unroll
        for (int i = 0; i < 8; i++) {
            float s = red[(0 * 64 + d) * 8 + i] + red[(1 * 64 + d) * 8 + i] +
                      red[(2 * 64 + d) * 8 + i] + red[(3 * 64 + d) * 8 + i];
            atomicAdd(&g_upd[(b * 8 + i) * 256 + h * 64 + d], s);
        }
    }
}

// ---------------- host ----------------
extern "C" void kernel_launch(void* const* d_in, const int* in_sizes, int n_in,
                              void* d_out, int out_size) {
    const float* inputs = (const float*)d_in[0];
    const float* slots0 = (const float*)d_in[1];
    const float* w_q = (const float*)d_in[2];
    const float* w_k = (const float*)d_in[3];
    const float* w_v = (const float*)d_in[4];
    const float* w_ih = (const float*)d_in[5];
    const float* w_hh = (const float*)d_in[6];
    const float* b_ih = (const float*)d_in[7];
    const float* b_hh = (const float*)d_in[8];
    const float* ln_in_g = (const float*)d_in[9];
    const float* ln_in_b = (const float*)d_in[10];
    const float* ln_s_g = (const float*)d_in[11];
    const float* ln_s_b = (const float*)d_in[12];
    const float* ln_ff_g = (const float*)d_in[13];
    const float* ln_ff_b = (const float*)d_in[14];
    const float* w_ff1 = (const float*)d_in[15];
    const float* b_ff1 = (const float*)d_in[16];
    const float* w_ff2 = (const float*)d_in[17];
    const float* b_ff2 = (const float*)d_in[18];
    float* out = (float*)d_out;

    void *slots_dev, *S_dev, *upd_dev, *x_dev, *q_dev, *upd2, *gi_dev, *gh_dev, *ff_dev;
    cudaGetSymbolAddress(&slots_dev, g_slots);
    cudaGetSymbolAddress(&S_dev, g_S);
    cudaGetSymbolAddress(&upd_dev, g_upd);
    cudaGetSymbolAddress(&x_dev, g_x);
    cudaGetSymbolAddress(&q_dev, g_q);
    cudaGetSymbolAddress(&gi_dev, g_gi);
    cudaGetSymbolAddress(&gh_dev, g_gh);
    cudaGetSymbolAddress(&ff_dev, g_ff);
    float* slots = (float*)slots_dev;
    float* xbuf = (float*)x_dev;
    float* qbuf = (float*)q_dev;
    float* updb = (float*)upd_dev;
    float* gib = (float*)gi_dev;
    float* ghb = (float*)gh_dev;
    float* ffb = (float*)ff_dev;

    cudaMemcpyAsync(slots_dev, slots0, 128 * 256 * sizeof(float), cudaMemcpyDeviceToDevice);
    prep_fold<<<512, 256>>>(w_k, w_v, ln_in_g, ln_in_b);
    kv_gemm_tc<<<dim3(4, (Bc * Nc) / 128), 256>>>(inputs);

    for (int it = 0; it < 3; it++) {
        ln_rows<<<128, 32>>>(slots, ln_s_g, ln_s_b, xbuf);
        colgemm<256, 0><<<128, 128>>>(xbuf, w_q, (const float*)0, qbuf, 256, (const float*)0);
        cudaMemsetAsync(S_dev, 0, 16 * 32 * sizeof(float));
        dots_kernel<<<dim3(32, 16), 128>>>((it == 2) ? (out + 128 * 256) : (float*)0);
        cudaMemsetAsync(upd_dev, 0, 128 * 256 * sizeof(float));
        upd_kernel<<<dim3(4, 4, 16), 256>>>();
        colgemm<256, 0><<<384, 128>>>(updb, w_ih, b_ih, gib, 768, (const float*)0);
        colgemm<256, 0><<<384, 128>>>(slots, w_hh, b_hh, ghb, 768, (const float*)0);
        gru_combine<<<128, 256>>>();
        ln_rows<<<128, 32>>>(slots, ln_ff_g, ln_ff_b, xbuf);
        colgemm<256, 1><<<512, 128>>>(xbuf, w_ff1, b_ff1, ffb, 1024, (const float*)0);
        colgemm<1024, 2><<<128, 128>>>(ffb, w_ff2, b_ff2, slots, 256, slots);
    }
    cudaMemcpyAsync(d_out, slots_dev, 128 * 256 * sizeof(float), cudaMemcpyDeviceToDevice);
}